// round 12
// baseline (speedup 1.0000x reference)
#include <cuda_runtime.h>
#include <math_constants.h>

#define BSZ 2
#define SEQ 2048
#define HID 1024
#define NH 16
#define HD 64
#define MTOT (BSZ * SEQ)   // 4096

__device__ float g_Q[BSZ * NH * SEQ * HD];
__device__ float g_K[BSZ * NH * SEQ * HD];
__device__ float g_V[BSZ * NH * SEQ * HD];
__device__ float g_ctx[BSZ * SEQ * HID];

// omega[j] = 10000^(-j/10)
__constant__ float c_om[10] = {
    1.0f, 0.3981071705534972f, 0.15848931924611134f, 0.06309573444801933f,
    0.025118864315095794f, 0.01f, 0.003981071705534973f,
    0.0015848931924611136f, 0.0006309573444801934f, 0.00025118864315095795f};

__device__ __forceinline__ unsigned f2tf32(float x) {
    unsigned r;
    asm("cvt.rna.tf32.f32 %0, %1;" : "=r"(r) : "f"(x));
    return r;
}

__device__ __forceinline__ void mma_tf32(float c[4], const unsigned a[4],
                                         unsigned b0, unsigned b1) {
    asm volatile(
        "mma.sync.aligned.m16n8k8.row.col.f32.tf32.tf32.f32 "
        "{%0,%1,%2,%3}, {%4,%5,%6,%7}, {%8,%9}, {%0,%1,%2,%3};\n"
        : "+f"(c[0]), "+f"(c[1]), "+f"(c[2]), "+f"(c[3])
        : "r"(a[0]), "r"(a[1]), "r"(a[2]), "r"(a[3]), "r"(b0), "r"(b1));
}

__device__ __forceinline__ void cp16(void* dst, const void* src) {
    unsigned d = (unsigned)__cvta_generic_to_shared(dst);
    asm volatile("cp.async.cg.shared.global [%0], [%1], 16;\n"
                 :: "r"(d), "l"(src));
}
#define CP_COMMIT() asm volatile("cp.async.commit_group;\n" ::: "memory")
#define CP_WAIT1()  asm volatile("cp.async.wait_group 1;\n" ::: "memory")
#define CP_WAIT0()  asm volatile("cp.async.wait_group 0;\n" ::: "memory")

// ---------------------------------------------------------------------------
// GEMM core (cp.async double-buffered, f32 smem, cvt at fragment load).
// ---------------------------------------------------------------------------
struct GemmCtx {
    float (*As)[128][36];
    float (*Bs)[32][136];
};

__device__ __forceinline__ void gemm_issue(
    const GemmCtx& cx, const float* A, const float* W,
    int m0, int n0, int k0, int bu, int tid)
{
#pragma unroll
    for (int it = 0; it < 4; it++) {
        int c = tid + it * 256;
        int row = c >> 3, cg = (c & 7) * 4;
        cp16(&cx.As[bu][row][cg], &A[(size_t)(m0 + row) * 1024 + k0 + cg]);
    }
#pragma unroll
    for (int it = 0; it < 4; it++) {
        int c = tid + it * 256;
        int row = c >> 5, cg = (c & 31) * 4;
        cp16(&cx.Bs[bu][row][cg], &W[(size_t)(k0 + row) * 1024 + n0 + cg]);
    }
    CP_COMMIT();
}

__device__ __forceinline__ void gemm_mainloop(
    const GemmCtx& cx, const float* A, const float* W,
    int m0, int n0, int wm, int wn, int g, int t, int tid,
    float acc[4][4][4])
{
#pragma unroll
    for (int mt = 0; mt < 4; mt++)
#pragma unroll
        for (int nt = 0; nt < 4; nt++)
#pragma unroll
            for (int i = 0; i < 4; i++) acc[mt][nt][i] = 0.f;

    gemm_issue(cx, A, W, m0, n0, 0, 0, tid);

    int cur = 0;
    for (int k0 = 0; k0 < 1024; k0 += 32) {
        __syncthreads();
        if (k0 + 32 < 1024) {
            gemm_issue(cx, A, W, m0, n0, k0 + 32, cur ^ 1, tid);
            CP_WAIT1();
        } else {
            CP_WAIT0();
        }
        __syncthreads();

#pragma unroll
        for (int ks = 0; ks < 4; ks++) {
            const int kk = ks * 8;
            unsigned af[4][4];
#pragma unroll
            for (int mt = 0; mt < 4; mt++) {
                int r = wm + mt * 16 + g;
                af[mt][0] = f2tf32(cx.As[cur][r][kk + t]);
                af[mt][1] = f2tf32(cx.As[cur][r + 8][kk + t]);
                af[mt][2] = f2tf32(cx.As[cur][r][kk + t + 4]);
                af[mt][3] = f2tf32(cx.As[cur][r + 8][kk + t + 4]);
            }
#pragma unroll
            for (int nt = 0; nt < 4; nt++) {
                unsigned b0 = f2tf32(cx.Bs[cur][kk + t][wn + nt * 8 + g]);
                unsigned b1 = f2tf32(cx.Bs[cur][kk + t + 4][wn + nt * 8 + g]);
#pragma unroll
                for (int mt = 0; mt < 4; mt++)
                    mma_tf32(acc[mt][nt], af[mt], b0, b1);
            }
        }
        cur ^= 1;
    }
}

// ---------------------------------------------------------------------------
// Fused QKV projection. Scatter [B,H,S,D]. RoPE on Q/K. Output stored as
// tf32 BIT PATTERNS (attention consumes them as mma operands directly).
// ---------------------------------------------------------------------------
__global__ void __launch_bounds__(256, 2) gemm_qkv_kernel(
    const float* __restrict__ A,
    const float* __restrict__ Wq, const float* __restrict__ Wk,
    const float* __restrict__ Wv,
    const float* __restrict__ bq, const float* __restrict__ bk,
    const float* __restrict__ bv,
    float* __restrict__ Qo, float* __restrict__ Ko, float* __restrict__ Vo)
{
    extern __shared__ float smg[];
    GemmCtx cx;
    cx.As = (float(*)[128][36])smg;
    cx.Bs = (float(*)[32][136])(smg + 2 * 128 * 36);

    const int z = blockIdx.z;
    const float* W = (z == 0) ? Wq : (z == 1) ? Wk : Wv;
    const float* bias = (z == 0) ? bq : (z == 1) ? bk : bv;
    float* C = (z == 0) ? Qo : (z == 1) ? Ko : Vo;
    const bool rope = (z < 2);

    const int tid = threadIdx.x;
    const int warp = tid >> 5, lane = tid & 31;
    const int g = lane >> 2, t = lane & 3;
    const int wm = (warp >> 2) * 64;
    const int wn = (warp & 3) * 32;
    const int m0 = blockIdx.y * 128;
    const int n0 = blockIdx.x * 128;

    float acc[4][4][4];
    gemm_mainloop(cx, A, W, m0, n0, wm, wn, g, t, tid, acc);

#pragma unroll
    for (int mt = 0; mt < 4; mt++) {
#pragma unroll
        for (int hi = 0; hi < 2; hi++) {
            int m = m0 + wm + mt * 16 + g + hi * 8;
            int s = m & (SEQ - 1);
            int frame = s >> 8;
            int rem = s & 255;
            int hp = rem >> 4;
            int wp = rem & 15;
#pragma unroll
            for (int nt = 0; nt < 4; nt++) {
                int n = n0 + wn + nt * 8 + 2 * t;
                float2 val;
                val.x = acc[mt][nt][hi * 2 + 0] + bias[n];
                val.y = acc[mt][nt][hi * 2 + 1] + bias[n + 1];
                int d = n & (HD - 1);
                if (rope && d < 60) {
                    int seg = d / 20;
                    int dl = d - seg * 20;      // even
                    int je = dl % 10;
                    float pos = (float)(seg == 0 ? frame : (seg == 1 ? hp : wp));
                    float se, ce, so, co;
                    __sincosf(pos * c_om[je], &se, &ce);
                    __sincosf(pos * c_om[je + 1], &so, &co);
                    float xo = val.x, yo = val.y;
                    val.x = xo * ce - yo * se;
                    val.y = yo * co + xo * so;
                }
                // store as tf32 bit pattern (RNA) — attention reads raw bits
                val.x = __uint_as_float(f2tf32(val.x));
                val.y = __uint_as_float(f2tf32(val.y));
                int b = m >> 11;
                int h = n >> 6;
                *(float2*)&C[((((size_t)b * NH + h) * SEQ + s) * HD) + d] = val;
            }
        }
    }
}

// ---------------------------------------------------------------------------
// Output projection: plain row-major out.
// ---------------------------------------------------------------------------
__global__ void __launch_bounds__(256, 2) gemm_out_kernel(
    const float* __restrict__ A, const float* __restrict__ W,
    const float* __restrict__ bias, float* __restrict__ C)
{
    extern __shared__ float smg[];
    GemmCtx cx;
    cx.As = (float(*)[128][36])smg;
    cx.Bs = (float(*)[32][136])(smg + 2 * 128 * 36);

    const int tid = threadIdx.x;
    const int warp = tid >> 5, lane = tid & 31;
    const int g = lane >> 2, t = lane & 3;
    const int wm = (warp >> 2) * 64;
    const int wn = (warp & 3) * 32;
    const int m0 = blockIdx.y * 128;
    const int n0 = blockIdx.x * 128;

    float acc[4][4][4];
    gemm_mainloop(cx, A, W, m0, n0, wm, wn, g, t, tid, acc);

#pragma unroll
    for (int mt = 0; mt < 4; mt++) {
#pragma unroll
        for (int hi = 0; hi < 2; hi++) {
            int m = m0 + wm + mt * 16 + g + hi * 8;
#pragma unroll
            for (int nt = 0; nt < 4; nt++) {
                int n = n0 + wn + nt * 8 + 2 * t;
                float2 val;
                val.x = acc[mt][nt][hi * 2 + 0] + bias[n];
                val.y = acc[mt][nt][hi * 2 + 1] + bias[n + 1];
                *(float2*)&C[(size_t)m * 1024 + n] = val;
            }
        }
    }
}

// ---------------------------------------------------------------------------
// Flash attention. 256 threads / 8 warps, 256 queries/block, 32 rows/warp
// (2 m-tiles -> B-fragment reuse x2). 64-key tiles, cp.async double-buffer.
// Q/K/V arrive as tf32 bit patterns -> NO cvt in mma loops.
// Smem (words): Qs[256][68] | Kr[2][64][72] | Vr[2][64][72] | Ss[256][68]
//   = 17408 + 9216 + 9216 + 17408 = 53248 words = 212,992 B
// ---------------------------------------------------------------------------
__global__ void __launch_bounds__(256) attn_tf32_kernel(
    const float* __restrict__ Q, const float* __restrict__ K,
    const float* __restrict__ V, float* __restrict__ ctx)
{
    extern __shared__ float smf[];
    unsigned (*Qs)[68] = (unsigned(*)[68])smf;
    float (*Kr)[64][72] = (float(*)[64][72])(smf + 256 * 68);
    float (*Vr)[64][72] = (float(*)[64][72])(smf + 256 * 68 + 2 * 64 * 72);
    unsigned (*Ss)[68] = (unsigned(*)[68])(smf + 256 * 68 + 4 * 64 * 72);

    const int tid = threadIdx.x;
    const int warp = tid >> 5, lane = tid & 31;
    const int g = lane >> 2, t = lane & 3;
    const int w32 = warp * 32;
    const int qt = blockIdx.x;
    const int h = blockIdx.y;
    const int b = blockIdx.z;

    const float* Qb = Q + (((size_t)b * NH + h) * SEQ + qt * 256) * HD;
    const float* Kb = K + ((size_t)b * NH + h) * SEQ * HD;
    const float* Vb = V + ((size_t)b * NH + h) * SEQ * HD;

    // K/V tile = 64 rows x 16 float4 = 1024 cp16 EACH -> 4 iters of 256 thr
    auto issue = [&](int j0, int bu) {
#pragma unroll
        for (int i = 0; i < 4; i++) {
            int c = tid + i * 256;            // 0..1023
            int row = c >> 4;                 // 0..63
            int col = (c & 15) * 4;
            cp16(&Kr[bu][row][col], Kb + (size_t)(j0 + row) * HD + col);
            cp16(&Vr[bu][row][col], Vb + (size_t)(j0 + row) * HD + col);
        }
        CP_COMMIT();
    };

    issue(0, 0);

    // Q tile 256x64: already tf32 bits, raw copy
#pragma unroll
    for (int it = 0; it < 16; it++) {
        int l = tid + it * 256;
        int row = l >> 4;
        int cg = (l & 15) * 4;
        float4 v = *(const float4*)&Qb[(size_t)row * HD + cg];
        Qs[row][cg + 0] = __float_as_uint(v.x);
        Qs[row][cg + 1] = __float_as_uint(v.y);
        Qs[row][cg + 2] = __float_as_uint(v.z);
        Qs[row][cg + 3] = __float_as_uint(v.w);
    }

    float m_i[4], l_i[4], o[2][8][4];
#pragma unroll
    for (int i = 0; i < 4; i++) { m_i[i] = -CUDART_INF_F; l_i[i] = 0.f; }
#pragma unroll
    for (int mt = 0; mt < 2; mt++)
#pragma unroll
        for (int nt = 0; nt < 8; nt++)
#pragma unroll
            for (int i = 0; i < 4; i++) o[mt][nt][i] = 0.f;

    for (int jt = 0; jt < SEQ / 64; jt++) {
        const int bu = jt & 1;
        __syncthreads();                       // prev compute done (+Q visible)
        if (jt + 1 < SEQ / 64) {
            issue((jt + 1) * 64, bu ^ 1);
            CP_WAIT1();
        } else {
            CP_WAIT0();
        }
        __syncthreads();                       // buffer bu visible

        // S = Q K^T  (raw tf32 bits, no cvt)
        float sc[2][8][4];
#pragma unroll
        for (int mt = 0; mt < 2; mt++)
#pragma unroll
            for (int nt = 0; nt < 8; nt++)
#pragma unroll
                for (int i = 0; i < 4; i++) sc[mt][nt][i] = 0.f;

#pragma unroll
        for (int ks = 0; ks < 8; ks++) {
            const int kk = ks * 8;
            unsigned af[2][4];
#pragma unroll
            for (int mt = 0; mt < 2; mt++) {
                int r = w32 + mt * 16 + g;
                af[mt][0] = Qs[r][kk + t];
                af[mt][1] = Qs[r + 8][kk + t];
                af[mt][2] = Qs[r][kk + t + 4];
                af[mt][3] = Qs[r + 8][kk + t + 4];
            }
#pragma unroll
            for (int nt = 0; nt < 8; nt++) {
                unsigned b0 = __float_as_uint(Kr[bu][nt * 8 + g][kk + t]);
                unsigned b1 = __float_as_uint(Kr[bu][nt * 8 + g][kk + t + 4]);
#pragma unroll
                for (int mt = 0; mt < 2; mt++)
                    mma_tf32(sc[mt][nt], af[mt], b0, b1);
            }
        }

        // Online softmax; P (tf32) -> Ss
#pragma unroll
        for (int mt = 0; mt < 2; mt++) {
#pragma unroll
            for (int hi = 0; hi < 2; hi++) {
                const int ri = mt * 2 + hi;
                float pm = -CUDART_INF_F;
#pragma unroll
                for (int nt = 0; nt < 8; nt++) {
                    sc[mt][nt][hi * 2 + 0] *= 0.125f;
                    sc[mt][nt][hi * 2 + 1] *= 0.125f;
                    pm = fmaxf(pm, fmaxf(sc[mt][nt][hi * 2], sc[mt][nt][hi * 2 + 1]));
                }
                pm = fmaxf(pm, __shfl_xor_sync(0xffffffffu, pm, 1));
                pm = fmaxf(pm, __shfl_xor_sync(0xffffffffu, pm, 2));

                float mn = fmaxf(m_i[ri], pm);
                float corr = __expf(m_i[ri] - mn);
                m_i[ri] = mn;

                float ps = 0.f;
                int row = w32 + mt * 16 + g + hi * 8;
#pragma unroll
                for (int nt = 0; nt < 8; nt++) {
                    float p0 = __expf(sc[mt][nt][hi * 2 + 0] - mn);
                    float p1 = __expf(sc[mt][nt][hi * 2 + 1] - mn);
                    ps += p0 + p1;
                    Ss[row][nt * 8 + 2 * t + 0] = f2tf32(p0);
                    Ss[row][nt * 8 + 2 * t + 1] = f2tf32(p1);
                }
                ps += __shfl_xor_sync(0xffffffffu, ps, 1);
                ps += __shfl_xor_sync(0xffffffffu, ps, 2);
                l_i[ri] = l_i[ri] * corr + ps;

#pragma unroll
                for (int nt = 0; nt < 8; nt++) {
                    o[mt][nt][hi * 2 + 0] *= corr;
                    o[mt][nt][hi * 2 + 1] *= corr;
                }
            }
        }
        __syncwarp();

        // O += P V  (V raw tf32 bits)
#pragma unroll
        for (int ks = 0; ks < 8; ks++) {
            const int kk = ks * 8;
            unsigned af[2][4];
#pragma unroll
            for (int mt = 0; mt < 2; mt++) {
                int r = w32 + mt * 16 + g;
                af[mt][0] = Ss[r][kk + t];
                af[mt][1] = Ss[r + 8][kk + t];
                af[mt][2] = Ss[r][kk + t + 4];
                af[mt][3] = Ss[r + 8][kk + t + 4];
            }
#pragma unroll
            for (int nt = 0; nt < 8; nt++) {
                unsigned b0 = __float_as_uint(Vr[bu][kk + t][nt * 8 + g]);
                unsigned b1 = __float_as_uint(Vr[bu][kk + t + 4][nt * 8 + g]);
#pragma unroll
                for (int mt = 0; mt < 2; mt++)
                    mma_tf32(o[mt][nt], af[mt], b0, b1);
            }
        }
    }

    // Epilogue: ctx [B,S,HID] (plain f32)
#pragma unroll
    for (int mt = 0; mt < 2; mt++) {
#pragma unroll
        for (int hi = 0; hi < 2; hi++) {
            const int ri = mt * 2 + hi;
            float inv = 1.f / l_i[ri];
            int srow = qt * 256 + w32 + mt * 16 + g + hi * 8;
#pragma unroll
            for (int nt = 0; nt < 8; nt++) {
                float2 val;
                val.x = o[mt][nt][hi * 2 + 0] * inv;
                val.y = o[mt][nt][hi * 2 + 1] * inv;
                *(float2*)&ctx[((size_t)b * SEQ + srow) * HID + h * HD + nt * 8 + 2 * t] = val;
            }
        }
    }
}

// ---------------------------------------------------------------------------
extern "C" void kernel_launch(void* const* d_in, const int* in_sizes, int n_in,
                              void* d_out, int out_size)
{
    const float* hidden = (const float*)d_in[0];
    const float* Wq = (const float*)d_in[1];
    const float* bq = (const float*)d_in[2];
    const float* Wk = (const float*)d_in[3];
    const float* bk = (const float*)d_in[4];
    const float* Wv = (const float*)d_in[5];
    const float* bv = (const float*)d_in[6];
    const float* Wo = (const float*)d_in[7];
    const float* bo = (const float*)d_in[8];
    float* out = (float*)d_out;

    float *pQ, *pK, *pV, *pCtx;
    cudaGetSymbolAddress((void**)&pQ, g_Q);
    cudaGetSymbolAddress((void**)&pK, g_K);
    cudaGetSymbolAddress((void**)&pV, g_V);
    cudaGetSymbolAddress((void**)&pCtx, g_ctx);

    const int gsmem = (2 * 128 * 36 + 2 * 32 * 136) * 4;   // 71,680 B
    cudaFuncSetAttribute(gemm_qkv_kernel,
                         cudaFuncAttributeMaxDynamicSharedMemorySize, gsmem);
    cudaFuncSetAttribute(gemm_out_kernel,
                         cudaFuncAttributeMaxDynamicSharedMemorySize, gsmem);

    // Fused QKV projection (+bias, +RoPE, -> tf32 bits), scatter [B,H,S,D]
    dim3 qgrid(HID / 128, MTOT / 128, 3);   // (8, 32, 3)
    gemm_qkv_kernel<<<qgrid, 256, gsmem>>>(hidden, Wq, Wk, Wv, bq, bk, bv,
                                           pQ, pK, pV);

    // Attention
    {
        const int smem_bytes = (256 * 68 + 4 * 64 * 72 + 256 * 68) * 4;  // 212,992
        cudaFuncSetAttribute(attn_tf32_kernel,
                             cudaFuncAttributeMaxDynamicSharedMemorySize,
                             smem_bytes);
        dim3 agrid(SEQ / 256, NH, BSZ);  // (8, 16, 2)
        attn_tf32_kernel<<<agrid, 256, smem_bytes>>>(pQ, pK, pV, pCtx);
    }

    // Output projection
    dim3 ogrid(HID / 128, MTOT / 128);
    gemm_out_kernel<<<ogrid, 256, gsmem>>>(pCtx, Wo, bo, out);
}

// round 15
// speedup vs baseline: 1.4641x; 1.4641x over previous
#include <cuda_runtime.h>
#include <math_constants.h>

#define BSZ 2
#define SEQ 2048
#define HID 1024
#define NH 16
#define HD 64
#define MTOT (BSZ * SEQ)   // 4096

__device__ float g_Q[BSZ * NH * SEQ * HD];
__device__ float g_K[BSZ * NH * SEQ * HD];
__device__ float g_V[BSZ * NH * SEQ * HD];
__device__ float g_ctx[BSZ * SEQ * HID];

// omega[j] = 10000^(-j/10)
__constant__ float c_om[10] = {
    1.0f, 0.3981071705534972f, 0.15848931924611134f, 0.06309573444801933f,
    0.025118864315095794f, 0.01f, 0.003981071705534973f,
    0.0015848931924611136f, 0.0006309573444801934f, 0.00025118864315095795f};

__device__ __forceinline__ unsigned f2tf32(float x) {
    unsigned r;
    asm("cvt.rna.tf32.f32 %0, %1;" : "=r"(r) : "f"(x));
    return r;
}

__device__ __forceinline__ void mma_tf32(float c[4], const unsigned a[4],
                                         unsigned b0, unsigned b1) {
    asm volatile(
        "mma.sync.aligned.m16n8k8.row.col.f32.tf32.tf32.f32 "
        "{%0,%1,%2,%3}, {%4,%5,%6,%7}, {%8,%9}, {%0,%1,%2,%3};\n"
        : "+f"(c[0]), "+f"(c[1]), "+f"(c[2]), "+f"(c[3])
        : "r"(a[0]), "r"(a[1]), "r"(a[2]), "r"(a[3]), "r"(b0), "r"(b1));
}

__device__ __forceinline__ void cp16(void* dst, const void* src) {
    unsigned d = (unsigned)__cvta_generic_to_shared(dst);
    asm volatile("cp.async.cg.shared.global [%0], [%1], 16;\n"
                 :: "r"(d), "l"(src));
}
#define CP_COMMIT() asm volatile("cp.async.commit_group;\n" ::: "memory")
#define CP_WAIT1()  asm volatile("cp.async.wait_group 1;\n" ::: "memory")
#define CP_WAIT0()  asm volatile("cp.async.wait_group 0;\n" ::: "memory")

// ---------------------------------------------------------------------------
// GEMM core (cp.async double-buffered, f32 smem, cvt at fragment load).
// ---------------------------------------------------------------------------
struct GemmCtx {
    float (*As)[128][36];
    float (*Bs)[32][136];
};

__device__ __forceinline__ void gemm_issue(
    const GemmCtx& cx, const float* A, const float* W,
    int m0, int n0, int k0, int bu, int tid)
{
#pragma unroll
    for (int it = 0; it < 4; it++) {          // A: 128x8 float4 = 1024 = 4x256
        int c = tid + it * 256;
        int row = c >> 3, cg = (c & 7) * 4;
        cp16(&cx.As[bu][row][cg], &A[(size_t)(m0 + row) * 1024 + k0 + cg]);
    }
#pragma unroll
    for (int it = 0; it < 4; it++) {          // B: 32x32 float4 = 1024 = 4x256
        int c = tid + it * 256;
        int row = c >> 5, cg = (c & 31) * 4;
        cp16(&cx.Bs[bu][row][cg], &W[(size_t)(k0 + row) * 1024 + n0 + cg]);
    }
    CP_COMMIT();
}

__device__ __forceinline__ void gemm_mainloop(
    const GemmCtx& cx, const float* A, const float* W,
    int m0, int n0, int wm, int wn, int g, int t, int tid,
    float acc[4][4][4])
{
#pragma unroll
    for (int mt = 0; mt < 4; mt++)
#pragma unroll
        for (int nt = 0; nt < 4; nt++)
#pragma unroll
            for (int i = 0; i < 4; i++) acc[mt][nt][i] = 0.f;

    gemm_issue(cx, A, W, m0, n0, 0, 0, tid);

    int cur = 0;
    for (int k0 = 0; k0 < 1024; k0 += 32) {
        __syncthreads();
        if (k0 + 32 < 1024) {
            gemm_issue(cx, A, W, m0, n0, k0 + 32, cur ^ 1, tid);
            CP_WAIT1();
        } else {
            CP_WAIT0();
        }
        __syncthreads();

#pragma unroll
        for (int ks = 0; ks < 4; ks++) {
            const int kk = ks * 8;
            unsigned af[4][4];
#pragma unroll
            for (int mt = 0; mt < 4; mt++) {
                int r = wm + mt * 16 + g;
                af[mt][0] = f2tf32(cx.As[cur][r][kk + t]);
                af[mt][1] = f2tf32(cx.As[cur][r + 8][kk + t]);
                af[mt][2] = f2tf32(cx.As[cur][r][kk + t + 4]);
                af[mt][3] = f2tf32(cx.As[cur][r + 8][kk + t + 4]);
            }
#pragma unroll
            for (int nt = 0; nt < 4; nt++) {
                unsigned b0 = f2tf32(cx.Bs[cur][kk + t][wn + nt * 8 + g]);
                unsigned b1 = f2tf32(cx.Bs[cur][kk + t + 4][wn + nt * 8 + g]);
#pragma unroll
                for (int mt = 0; mt < 4; mt++)
                    mma_tf32(acc[mt][nt], af[mt], b0, b1);
            }
        }
        cur ^= 1;
    }
}

// ---------------------------------------------------------------------------
// Fused QKV projection. Scatter [B,H,S,D]. RoPE on Q/K. Output stored as
// tf32 BIT PATTERNS (attention consumes them as mma operands directly).
// ---------------------------------------------------------------------------
__global__ void __launch_bounds__(256, 2) gemm_qkv_kernel(
    const float* __restrict__ A,
    const float* __restrict__ Wq, const float* __restrict__ Wk,
    const float* __restrict__ Wv,
    const float* __restrict__ bq, const float* __restrict__ bk,
    const float* __restrict__ bv,
    float* __restrict__ Qo, float* __restrict__ Ko, float* __restrict__ Vo)
{
    extern __shared__ float smg[];
    GemmCtx cx;
    cx.As = (float(*)[128][36])smg;
    cx.Bs = (float(*)[32][136])(smg + 2 * 128 * 36);

    const int z = blockIdx.z;
    const float* W = (z == 0) ? Wq : (z == 1) ? Wk : Wv;
    const float* bias = (z == 0) ? bq : (z == 1) ? bk : bv;
    float* C = (z == 0) ? Qo : (z == 1) ? Ko : Vo;
    const bool rope = (z < 2);

    const int tid = threadIdx.x;
    const int warp = tid >> 5, lane = tid & 31;
    const int g = lane >> 2, t = lane & 3;
    const int wm = (warp >> 2) * 64;
    const int wn = (warp & 3) * 32;
    const int m0 = blockIdx.y * 128;
    const int n0 = blockIdx.x * 128;

    float acc[4][4][4];
    gemm_mainloop(cx, A, W, m0, n0, wm, wn, g, t, tid, acc);

#pragma unroll
    for (int mt = 0; mt < 4; mt++) {
#pragma unroll
        for (int hi = 0; hi < 2; hi++) {
            int m = m0 + wm + mt * 16 + g + hi * 8;
            int s = m & (SEQ - 1);
            int frame = s >> 8;
            int rem = s & 255;
            int hp = rem >> 4;
            int wp = rem & 15;
#pragma unroll
            for (int nt = 0; nt < 4; nt++) {
                int n = n0 + wn + nt * 8 + 2 * t;
                float2 val;
                val.x = acc[mt][nt][hi * 2 + 0] + bias[n];
                val.y = acc[mt][nt][hi * 2 + 1] + bias[n + 1];
                int d = n & (HD - 1);
                if (rope && d < 60) {
                    int seg = d / 20;
                    int dl = d - seg * 20;      // even
                    int je = dl % 10;
                    float pos = (float)(seg == 0 ? frame : (seg == 1 ? hp : wp));
                    float se, ce, so, co;
                    __sincosf(pos * c_om[je], &se, &ce);
                    __sincosf(pos * c_om[je + 1], &so, &co);
                    float xo = val.x, yo = val.y;
                    val.x = xo * ce - yo * se;
                    val.y = yo * co + xo * so;
                }
                // store as tf32 bit pattern (RNA) — attention reads raw bits
                val.x = __uint_as_float(f2tf32(val.x));
                val.y = __uint_as_float(f2tf32(val.y));
                int b = m >> 11;
                int h = n >> 6;
                *(float2*)&C[((((size_t)b * NH + h) * SEQ + s) * HD) + d] = val;
            }
        }
    }
}

// ---------------------------------------------------------------------------
// Output projection: plain row-major out.
// ---------------------------------------------------------------------------
__global__ void __launch_bounds__(256, 2) gemm_out_kernel(
    const float* __restrict__ A, const float* __restrict__ W,
    const float* __restrict__ bias, float* __restrict__ C)
{
    extern __shared__ float smg[];
    GemmCtx cx;
    cx.As = (float(*)[128][36])smg;
    cx.Bs = (float(*)[32][136])(smg + 2 * 128 * 36);

    const int tid = threadIdx.x;
    const int warp = tid >> 5, lane = tid & 31;
    const int g = lane >> 2, t = lane & 3;
    const int wm = (warp >> 2) * 64;
    const int wn = (warp & 3) * 32;
    const int m0 = blockIdx.y * 128;
    const int n0 = blockIdx.x * 128;

    float acc[4][4][4];
    gemm_mainloop(cx, A, W, m0, n0, wm, wn, g, t, tid, acc);

#pragma unroll
    for (int mt = 0; mt < 4; mt++) {
#pragma unroll
        for (int hi = 0; hi < 2; hi++) {
            int m = m0 + wm + mt * 16 + g + hi * 8;
#pragma unroll
            for (int nt = 0; nt < 4; nt++) {
                int n = n0 + wn + nt * 8 + 2 * t;
                float2 val;
                val.x = acc[mt][nt][hi * 2 + 0] + bias[n];
                val.y = acc[mt][nt][hi * 2 + 1] + bias[n + 1];
                *(float2*)&C[(size_t)m * 1024 + n] = val;
            }
        }
    }
}

// ---------------------------------------------------------------------------
// Flash attention — round-5 structure + tf32-bits-at-rest (zero cvt in mma
// loops). 128 threads / 4 warps, 128 queries/block, 32 rows/warp.
// COVERAGE: Q tile 128x16 float4 = 2048 = 16 it x 128 thr.
//           K/V tiles 64x16 float4 = 1024 = 8 it x 128 thr each.
// Smem (words): Qs[128][68] | Kr[2][64][72] | Vr[2][64][72] | Ss[128][68]
//   -> 143,360 B
// ---------------------------------------------------------------------------
__global__ void __launch_bounds__(128) attn_tf32_kernel(
    const float* __restrict__ Q, const float* __restrict__ K,
    const float* __restrict__ V, float* __restrict__ ctx)
{
    extern __shared__ float smf[];
    unsigned (*Qs)[68] = (unsigned(*)[68])smf;
    float (*Kr)[64][72] = (float(*)[64][72])(smf + 128 * 68);
    float (*Vr)[64][72] = (float(*)[64][72])(smf + 128 * 68 + 2 * 64 * 72);
    unsigned (*Ss)[68] = (unsigned(*)[68])(smf + 128 * 68 + 4 * 64 * 72);

    const int tid = threadIdx.x;
    const int warp = tid >> 5, lane = tid & 31;
    const int g = lane >> 2, t = lane & 3;
    const int w32 = warp * 32;
    const int qt = blockIdx.x;
    const int h = blockIdx.y;
    const int b = blockIdx.z;

    const float* Qb = Q + (((size_t)b * NH + h) * SEQ + qt * 128) * HD;
    const float* Kb = K + ((size_t)b * NH + h) * SEQ * HD;
    const float* Vb = V + ((size_t)b * NH + h) * SEQ * HD;

    // K/V tile = 64 rows x 16 float4 = 1024 cp16 each -> 8 iters of 128 thr
    auto issue = [&](int j0, int bu) {
#pragma unroll
        for (int i = 0; i < 8; i++) {
            int c = tid + i * 128;            // 0..1023
            int row = c >> 4;                 // 0..63
            int col = (c & 15) * 4;
            cp16(&Kr[bu][row][col], Kb + (size_t)(j0 + row) * HD + col);
            cp16(&Vr[bu][row][col], Vb + (size_t)(j0 + row) * HD + col);
        }
        CP_COMMIT();
    };

    issue(0, 0);

    // Q tile 128 rows x 16 float4 = 2048 loads -> 16 iters of 128 threads
#pragma unroll
    for (int it = 0; it < 16; it++) {
        int l = tid + it * 128;               // 0..2047
        int row = l >> 4;                     // 0..127
        int cg = (l & 15) * 4;
        float4 v = *(const float4*)&Qb[(size_t)row * HD + cg];
        Qs[row][cg + 0] = __float_as_uint(v.x);
        Qs[row][cg + 1] = __float_as_uint(v.y);
        Qs[row][cg + 2] = __float_as_uint(v.z);
        Qs[row][cg + 3] = __float_as_uint(v.w);
    }

    float m_i[4], l_i[4], o[2][8][4];
#pragma unroll
    for (int i = 0; i < 4; i++) { m_i[i] = -CUDART_INF_F; l_i[i] = 0.f; }
#pragma unroll
    for (int mt = 0; mt < 2; mt++)
#pragma unroll
        for (int nt = 0; nt < 8; nt++)
#pragma unroll
            for (int i = 0; i < 4; i++) o[mt][nt][i] = 0.f;

    for (int jt = 0; jt < SEQ / 64; jt++) {
        const int bu = jt & 1;
        __syncthreads();                       // prev compute done (+Q visible)
        if (jt + 1 < SEQ / 64) {
            issue((jt + 1) * 64, bu ^ 1);
            CP_WAIT1();
        } else {
            CP_WAIT0();
        }
        __syncthreads();                       // buffer bu visible

        // S = Q K^T  (raw tf32 bits, no cvt)
        float sc[2][8][4];
#pragma unroll
        for (int mt = 0; mt < 2; mt++)
#pragma unroll
            for (int nt = 0; nt < 8; nt++)
#pragma unroll
                for (int i = 0; i < 4; i++) sc[mt][nt][i] = 0.f;

#pragma unroll
        for (int ks = 0; ks < 8; ks++) {
            const int kk = ks * 8;
            unsigned af[2][4];
#pragma unroll
            for (int mt = 0; mt < 2; mt++) {
                int r = w32 + mt * 16 + g;
                af[mt][0] = Qs[r][kk + t];
                af[mt][1] = Qs[r + 8][kk + t];
                af[mt][2] = Qs[r][kk + t + 4];
                af[mt][3] = Qs[r + 8][kk + t + 4];
            }
#pragma unroll
            for (int nt = 0; nt < 8; nt++) {
                unsigned b0 = __float_as_uint(Kr[bu][nt * 8 + g][kk + t]);
                unsigned b1 = __float_as_uint(Kr[bu][nt * 8 + g][kk + t + 4]);
#pragma unroll
                for (int mt = 0; mt < 2; mt++)
                    mma_tf32(sc[mt][nt], af[mt], b0, b1);
            }
        }

        // Online softmax; P (tf32) -> Ss
#pragma unroll
        for (int mt = 0; mt < 2; mt++) {
#pragma unroll
            for (int hi = 0; hi < 2; hi++) {
                const int ri = mt * 2 + hi;
                float pm = -CUDART_INF_F;
#pragma unroll
                for (int nt = 0; nt < 8; nt++) {
                    sc[mt][nt][hi * 2 + 0] *= 0.125f;
                    sc[mt][nt][hi * 2 + 1] *= 0.125f;
                    pm = fmaxf(pm, fmaxf(sc[mt][nt][hi * 2], sc[mt][nt][hi * 2 + 1]));
                }
                pm = fmaxf(pm, __shfl_xor_sync(0xffffffffu, pm, 1));
                pm = fmaxf(pm, __shfl_xor_sync(0xffffffffu, pm, 2));

                float mn = fmaxf(m_i[ri], pm);
                float corr = __expf(m_i[ri] - mn);
                m_i[ri] = mn;

                float ps = 0.f;
                int row = w32 + mt * 16 + g + hi * 8;
#pragma unroll
                for (int nt = 0; nt < 8; nt++) {
                    float p0 = __expf(sc[mt][nt][hi * 2 + 0] - mn);
                    float p1 = __expf(sc[mt][nt][hi * 2 + 1] - mn);
                    ps += p0 + p1;
                    Ss[row][nt * 8 + 2 * t + 0] = f2tf32(p0);
                    Ss[row][nt * 8 + 2 * t + 1] = f2tf32(p1);
                }
                ps += __shfl_xor_sync(0xffffffffu, ps, 1);
                ps += __shfl_xor_sync(0xffffffffu, ps, 2);
                l_i[ri] = l_i[ri] * corr + ps;

#pragma unroll
                for (int nt = 0; nt < 8; nt++) {
                    o[mt][nt][hi * 2 + 0] *= corr;
                    o[mt][nt][hi * 2 + 1] *= corr;
                }
            }
        }
        __syncwarp();

        // O += P V  (V raw tf32 bits)
#pragma unroll
        for (int ks = 0; ks < 8; ks++) {
            const int kk = ks * 8;
            unsigned af[2][4];
#pragma unroll
            for (int mt = 0; mt < 2; mt++) {
                int r = w32 + mt * 16 + g;
                af[mt][0] = Ss[r][kk + t];
                af[mt][1] = Ss[r + 8][kk + t];
                af[mt][2] = Ss[r][kk + t + 4];
                af[mt][3] = Ss[r + 8][kk + t + 4];
            }
#pragma unroll
            for (int nt = 0; nt < 8; nt++) {
                unsigned b0 = __float_as_uint(Vr[bu][kk + t][nt * 8 + g]);
                unsigned b1 = __float_as_uint(Vr[bu][kk + t + 4][nt * 8 + g]);
#pragma unroll
                for (int mt = 0; mt < 2; mt++)
                    mma_tf32(o[mt][nt], af[mt], b0, b1);
            }
        }
    }

    // Epilogue: ctx [B,S,HID] (plain f32)
#pragma unroll
    for (int mt = 0; mt < 2; mt++) {
#pragma unroll
        for (int hi = 0; hi < 2; hi++) {
            const int ri = mt * 2 + hi;
            float inv = 1.f / l_i[ri];
            int srow = qt * 128 + w32 + mt * 16 + g + hi * 8;
#pragma unroll
            for (int nt = 0; nt < 8; nt++) {
                float2 val;
                val.x = o[mt][nt][hi * 2 + 0] * inv;
                val.y = o[mt][nt][hi * 2 + 1] * inv;
                *(float2*)&ctx[((size_t)b * SEQ + srow) * HID + h * HD + nt * 8 + 2 * t] = val;
            }
        }
    }
}

// ---------------------------------------------------------------------------
extern "C" void kernel_launch(void* const* d_in, const int* in_sizes, int n_in,
                              void* d_out, int out_size)
{
    const float* hidden = (const float*)d_in[0];
    const float* Wq = (const float*)d_in[1];
    const float* bq = (const float*)d_in[2];
    const float* Wk = (const float*)d_in[3];
    const float* bk = (const float*)d_in[4];
    const float* Wv = (const float*)d_in[5];
    const float* bv = (const float*)d_in[6];
    const float* Wo = (const float*)d_in[7];
    const float* bo = (const float*)d_in[8];
    float* out = (float*)d_out;

    float *pQ, *pK, *pV, *pCtx;
    cudaGetSymbolAddress((void**)&pQ, g_Q);
    cudaGetSymbolAddress((void**)&pK, g_K);
    cudaGetSymbolAddress((void**)&pV, g_V);
    cudaGetSymbolAddress((void**)&pCtx, g_ctx);

    const int gsmem = (2 * 128 * 36 + 2 * 32 * 136) * 4;   // 71,680 B
    cudaFuncSetAttribute(gemm_qkv_kernel,
                         cudaFuncAttributeMaxDynamicSharedMemorySize, gsmem);
    cudaFuncSetAttribute(gemm_out_kernel,
                         cudaFuncAttributeMaxDynamicSharedMemorySize, gsmem);

    // Fused QKV projection (+bias, +RoPE, -> tf32 bits), scatter [B,H,S,D]
    dim3 qgrid(HID / 128, MTOT / 128, 3);   // (8, 32, 3)
    gemm_qkv_kernel<<<qgrid, 256, gsmem>>>(hidden, Wq, Wk, Wv, bq, bk, bv,
                                           pQ, pK, pV);

    // Attention (round-5 shape: 128 threads, 512 blocks)
    {
        const int smem_bytes = (128 * 68 + 4 * 64 * 72 + 128 * 68) * 4;  // 143,360
        cudaFuncSetAttribute(attn_tf32_kernel,
                             cudaFuncAttributeMaxDynamicSharedMemorySize,
                             smem_bytes);
        dim3 agrid(SEQ / 128, NH, BSZ);  // (16, 16, 2)
        attn_tf32_kernel<<<agrid, 128, smem_bytes>>>(pQ, pK, pV, pCtx);
    }

    // Output projection
    dim3 ogrid(HID / 128, MTOT / 128);
    gemm_out_kernel<<<ogrid, 256, gsmem>>>(pCtx, Wo, bo, out);
}

// round 16
// speedup vs baseline: 1.5338x; 1.0476x over previous
#include <cuda_runtime.h>
#include <math_constants.h>

#define BSZ 2
#define SEQ 2048
#define HID 1024
#define NH 16
#define HD 64
#define MTOT (BSZ * SEQ)   // 4096

__device__ float g_Q[BSZ * NH * SEQ * HD];
__device__ float g_K[BSZ * NH * SEQ * HD];
__device__ float g_V[BSZ * NH * SEQ * HD];
__device__ float g_ctx[BSZ * SEQ * HID];
__device__ float g_hidT[MTOT * HID];        // hidden as tf32 bits
__device__ float g_WT[4 * HID * HID];       // Wq,Wk,Wv,Wo as tf32 bits

// omega[j] = 10000^(-j/10)
__constant__ float c_om[10] = {
    1.0f, 0.3981071705534972f, 0.15848931924611134f, 0.06309573444801933f,
    0.025118864315095794f, 0.01f, 0.003981071705534973f,
    0.0015848931924611136f, 0.0006309573444801934f, 0.00025118864315095795f};

__device__ __forceinline__ unsigned f2tf32(float x) {
    unsigned r;
    asm("cvt.rna.tf32.f32 %0, %1;" : "=r"(r) : "f"(x));
    return r;
}

__device__ __forceinline__ void mma_tf32(float c[4], const unsigned a[4],
                                         unsigned b0, unsigned b1) {
    asm volatile(
        "mma.sync.aligned.m16n8k8.row.col.f32.tf32.tf32.f32 "
        "{%0,%1,%2,%3}, {%4,%5,%6,%7}, {%8,%9}, {%0,%1,%2,%3};\n"
        : "+f"(c[0]), "+f"(c[1]), "+f"(c[2]), "+f"(c[3])
        : "r"(a[0]), "r"(a[1]), "r"(a[2]), "r"(a[3]), "r"(b0), "r"(b1));
}

__device__ __forceinline__ void cp16(void* dst, const void* src) {
    unsigned d = (unsigned)__cvta_generic_to_shared(dst);
    asm volatile("cp.async.cg.shared.global [%0], [%1], 16;\n"
                 :: "r"(d), "l"(src));
}
#define CP_COMMIT() asm volatile("cp.async.commit_group;\n" ::: "memory")
#define CP_WAIT1()  asm volatile("cp.async.wait_group 1;\n" ::: "memory")
#define CP_WAIT0()  asm volatile("cp.async.wait_group 0;\n" ::: "memory")

// ---------------------------------------------------------------------------
// Pre-pass: convert hidden + 4 weight matrices to tf32 bit patterns.
// Total 8M floats = 2M float4. grid 8192 x 256.
// ---------------------------------------------------------------------------
__global__ void __launch_bounds__(256) cvt_tf32_kernel(
    const float* __restrict__ hid,
    const float* __restrict__ Wq, const float* __restrict__ Wk,
    const float* __restrict__ Wv, const float* __restrict__ Wo,
    float* __restrict__ hidT, float* __restrict__ WT)
{
    const int HID2 = HID * HID;              // 1M
    int i4 = blockIdx.x * blockDim.x + threadIdx.x;   // 0..2M-1
    long long e = (long long)i4 * 4;
    const float* src;
    float* dst;
    if (e < (long long)MTOT * HID) {                     // hidden: 4M
        src = hid + e;
        dst = hidT + e;
    } else {
        long long r = e - (long long)MTOT * HID;         // 0..4M-1 (weights)
        int w = (int)(r / HID2);
        long long off = r - (long long)w * HID2;
        src = ((w == 0) ? Wq : (w == 1) ? Wk : (w == 2) ? Wv : Wo) + off;
        dst = WT + (long long)w * HID2 + off;
    }
    float4 v = *(const float4*)src;
    v.x = __uint_as_float(f2tf32(v.x));
    v.y = __uint_as_float(f2tf32(v.y));
    v.z = __uint_as_float(f2tf32(v.z));
    v.w = __uint_as_float(f2tf32(v.w));
    *(float4*)dst = v;
}

// ---------------------------------------------------------------------------
// GEMM core (cp.async double-buffered). Operands are tf32 BIT PATTERNS ->
// mainloop has ZERO cvt instructions.
// ---------------------------------------------------------------------------
struct GemmCtx {
    unsigned (*As)[128][36];
    unsigned (*Bs)[32][136];
};

__device__ __forceinline__ void gemm_issue(
    const GemmCtx& cx, const float* A, const float* W,
    int m0, int n0, int k0, int bu, int tid)
{
#pragma unroll
    for (int it = 0; it < 4; it++) {          // A: 128x8 float4 = 1024 = 4x256
        int c = tid + it * 256;
        int row = c >> 3, cg = (c & 7) * 4;
        cp16(&cx.As[bu][row][cg], &A[(size_t)(m0 + row) * 1024 + k0 + cg]);
    }
#pragma unroll
    for (int it = 0; it < 4; it++) {          // B: 32x32 float4 = 1024 = 4x256
        int c = tid + it * 256;
        int row = c >> 5, cg = (c & 31) * 4;
        cp16(&cx.Bs[bu][row][cg], &W[(size_t)(k0 + row) * 1024 + n0 + cg]);
    }
    CP_COMMIT();
}

__device__ __forceinline__ void gemm_mainloop(
    const GemmCtx& cx, const float* A, const float* W,
    int m0, int n0, int wm, int wn, int g, int t, int tid,
    float acc[4][4][4])
{
#pragma unroll
    for (int mt = 0; mt < 4; mt++)
#pragma unroll
        for (int nt = 0; nt < 4; nt++)
#pragma unroll
            for (int i = 0; i < 4; i++) acc[mt][nt][i] = 0.f;

    gemm_issue(cx, A, W, m0, n0, 0, 0, tid);

    int cur = 0;
    for (int k0 = 0; k0 < 1024; k0 += 32) {
        __syncthreads();
        if (k0 + 32 < 1024) {
            gemm_issue(cx, A, W, m0, n0, k0 + 32, cur ^ 1, tid);
            CP_WAIT1();
        } else {
            CP_WAIT0();
        }
        __syncthreads();

#pragma unroll
        for (int ks = 0; ks < 4; ks++) {
            const int kk = ks * 8;
            unsigned af[4][4];
#pragma unroll
            for (int mt = 0; mt < 4; mt++) {
                int r = wm + mt * 16 + g;
                af[mt][0] = cx.As[cur][r][kk + t];
                af[mt][1] = cx.As[cur][r + 8][kk + t];
                af[mt][2] = cx.As[cur][r][kk + t + 4];
                af[mt][3] = cx.As[cur][r + 8][kk + t + 4];
            }
#pragma unroll
            for (int nt = 0; nt < 4; nt++) {
                unsigned b0 = cx.Bs[cur][kk + t][wn + nt * 8 + g];
                unsigned b1 = cx.Bs[cur][kk + t + 4][wn + nt * 8 + g];
#pragma unroll
                for (int mt = 0; mt < 4; mt++)
                    mma_tf32(acc[mt][nt], af[mt], b0, b1);
            }
        }
        cur ^= 1;
    }
}

// ---------------------------------------------------------------------------
// Fused QKV projection from pre-converted operands. Scatter [B,H,S,D].
// RoPE on Q/K. Output stored as tf32 bit patterns.
// ---------------------------------------------------------------------------
__global__ void __launch_bounds__(256, 2) gemm_qkv_kernel(
    const float* __restrict__ AT, const float* __restrict__ WT,
    const float* __restrict__ bq, const float* __restrict__ bk,
    const float* __restrict__ bv,
    float* __restrict__ Qo, float* __restrict__ Ko, float* __restrict__ Vo)
{
    extern __shared__ unsigned smg[];
    GemmCtx cx;
    cx.As = (unsigned(*)[128][36])smg;
    cx.Bs = (unsigned(*)[32][136])(smg + 2 * 128 * 36);

    const int z = blockIdx.z;
    const float* W = WT + (size_t)z * HID * HID;
    const float* bias = (z == 0) ? bq : (z == 1) ? bk : bv;
    float* C = (z == 0) ? Qo : (z == 1) ? Ko : Vo;
    const bool rope = (z < 2);

    const int tid = threadIdx.x;
    const int warp = tid >> 5, lane = tid & 31;
    const int g = lane >> 2, t = lane & 3;
    const int wm = (warp >> 2) * 64;
    const int wn = (warp & 3) * 32;
    const int m0 = blockIdx.y * 128;
    const int n0 = blockIdx.x * 128;

    float acc[4][4][4];
    gemm_mainloop(cx, AT, W, m0, n0, wm, wn, g, t, tid, acc);

#pragma unroll
    for (int mt = 0; mt < 4; mt++) {
#pragma unroll
        for (int hi = 0; hi < 2; hi++) {
            int m = m0 + wm + mt * 16 + g + hi * 8;
            int s = m & (SEQ - 1);
            int frame = s >> 8;
            int rem = s & 255;
            int hp = rem >> 4;
            int wp = rem & 15;
#pragma unroll
            for (int nt = 0; nt < 4; nt++) {
                int n = n0 + wn + nt * 8 + 2 * t;
                float2 val;
                val.x = acc[mt][nt][hi * 2 + 0] + bias[n];
                val.y = acc[mt][nt][hi * 2 + 1] + bias[n + 1];
                int d = n & (HD - 1);
                if (rope && d < 60) {
                    int seg = d / 20;
                    int dl = d - seg * 20;      // even
                    int je = dl % 10;
                    float pos = (float)(seg == 0 ? frame : (seg == 1 ? hp : wp));
                    float se, ce, so, co;
                    __sincosf(pos * c_om[je], &se, &ce);
                    __sincosf(pos * c_om[je + 1], &so, &co);
                    float xo = val.x, yo = val.y;
                    val.x = xo * ce - yo * se;
                    val.y = yo * co + xo * so;
                }
                // store as tf32 bit pattern — attention reads raw bits
                val.x = __uint_as_float(f2tf32(val.x));
                val.y = __uint_as_float(f2tf32(val.y));
                int b = m >> 11;
                int h = n >> 6;
                *(float2*)&C[((((size_t)b * NH + h) * SEQ + s) * HD) + d] = val;
            }
        }
    }
}

// ---------------------------------------------------------------------------
// Output projection: A = ctx (already tf32 bits from attention epilogue),
// W = pre-converted Wo. Plain row-major fp32 out.
// ---------------------------------------------------------------------------
__global__ void __launch_bounds__(256, 2) gemm_out_kernel(
    const float* __restrict__ AT, const float* __restrict__ WT,
    const float* __restrict__ bias, float* __restrict__ C)
{
    extern __shared__ unsigned smg[];
    GemmCtx cx;
    cx.As = (unsigned(*)[128][36])smg;
    cx.Bs = (unsigned(*)[32][136])(smg + 2 * 128 * 36);

    const int tid = threadIdx.x;
    const int warp = tid >> 5, lane = tid & 31;
    const int g = lane >> 2, t = lane & 3;
    const int wm = (warp >> 2) * 64;
    const int wn = (warp & 3) * 32;
    const int m0 = blockIdx.y * 128;
    const int n0 = blockIdx.x * 128;

    float acc[4][4][4];
    gemm_mainloop(cx, AT, WT, m0, n0, wm, wn, g, t, tid, acc);

#pragma unroll
    for (int mt = 0; mt < 4; mt++) {
#pragma unroll
        for (int hi = 0; hi < 2; hi++) {
            int m = m0 + wm + mt * 16 + g + hi * 8;
#pragma unroll
            for (int nt = 0; nt < 4; nt++) {
                int n = n0 + wn + nt * 8 + 2 * t;
                float2 val;
                val.x = acc[mt][nt][hi * 2 + 0] + bias[n];
                val.y = acc[mt][nt][hi * 2 + 1] + bias[n + 1];
                *(float2*)&C[(size_t)m * 1024 + n] = val;
            }
        }
    }
}

// ---------------------------------------------------------------------------
// Flash attention — 128 threads / 4 warps, 128 queries/block, 32 rows/warp.
// Q/K/V are tf32 bits; ctx written as tf32 bits for the O-projection.
// COVERAGE: Q tile 128x16 float4 = 2048 = 16 it x 128 thr.
//           K/V tiles 64x16 float4 = 1024 = 8 it x 128 thr each.
// Smem (words): Qs[128][68] | Kr[2][64][72] | Vr[2][64][72] | Ss[128][68]
//   -> 143,360 B
// ---------------------------------------------------------------------------
__global__ void __launch_bounds__(128) attn_tf32_kernel(
    const float* __restrict__ Q, const float* __restrict__ K,
    const float* __restrict__ V, float* __restrict__ ctx)
{
    extern __shared__ float smf[];
    unsigned (*Qs)[68] = (unsigned(*)[68])smf;
    float (*Kr)[64][72] = (float(*)[64][72])(smf + 128 * 68);
    float (*Vr)[64][72] = (float(*)[64][72])(smf + 128 * 68 + 2 * 64 * 72);
    unsigned (*Ss)[68] = (unsigned(*)[68])(smf + 128 * 68 + 4 * 64 * 72);

    const int tid = threadIdx.x;
    const int warp = tid >> 5, lane = tid & 31;
    const int g = lane >> 2, t = lane & 3;
    const int w32 = warp * 32;
    const int qt = blockIdx.x;
    const int h = blockIdx.y;
    const int b = blockIdx.z;

    const float* Qb = Q + (((size_t)b * NH + h) * SEQ + qt * 128) * HD;
    const float* Kb = K + ((size_t)b * NH + h) * SEQ * HD;
    const float* Vb = V + ((size_t)b * NH + h) * SEQ * HD;

    auto issue = [&](int j0, int bu) {
#pragma unroll
        for (int i = 0; i < 8; i++) {
            int c = tid + i * 128;            // 0..1023
            int row = c >> 4;                 // 0..63
            int col = (c & 15) * 4;
            cp16(&Kr[bu][row][col], Kb + (size_t)(j0 + row) * HD + col);
            cp16(&Vr[bu][row][col], Vb + (size_t)(j0 + row) * HD + col);
        }
        CP_COMMIT();
    };

    issue(0, 0);

    // Q tile 128 rows x 16 float4 = 2048 loads -> 16 iters of 128 threads
#pragma unroll
    for (int it = 0; it < 16; it++) {
        int l = tid + it * 128;               // 0..2047
        int row = l >> 4;                     // 0..127
        int cg = (l & 15) * 4;
        float4 v = *(const float4*)&Qb[(size_t)row * HD + cg];
        Qs[row][cg + 0] = __float_as_uint(v.x);
        Qs[row][cg + 1] = __float_as_uint(v.y);
        Qs[row][cg + 2] = __float_as_uint(v.z);
        Qs[row][cg + 3] = __float_as_uint(v.w);
    }

    float m_i[4], l_i[4], o[2][8][4];
#pragma unroll
    for (int i = 0; i < 4; i++) { m_i[i] = -CUDART_INF_F; l_i[i] = 0.f; }
#pragma unroll
    for (int mt = 0; mt < 2; mt++)
#pragma unroll
        for (int nt = 0; nt < 8; nt++)
#pragma unroll
            for (int i = 0; i < 4; i++) o[mt][nt][i] = 0.f;

    for (int jt = 0; jt < SEQ / 64; jt++) {
        const int bu = jt & 1;
        __syncthreads();                       // prev compute done (+Q visible)
        if (jt + 1 < SEQ / 64) {
            issue((jt + 1) * 64, bu ^ 1);
            CP_WAIT1();
        } else {
            CP_WAIT0();
        }
        __syncthreads();                       // buffer bu visible

        // S = Q K^T  (raw tf32 bits, no cvt)
        float sc[2][8][4];
#pragma unroll
        for (int mt = 0; mt < 2; mt++)
#pragma unroll
            for (int nt = 0; nt < 8; nt++)
#pragma unroll
                for (int i = 0; i < 4; i++) sc[mt][nt][i] = 0.f;

#pragma unroll
        for (int ks = 0; ks < 8; ks++) {
            const int kk = ks * 8;
            unsigned af[2][4];
#pragma unroll
            for (int mt = 0; mt < 2; mt++) {
                int r = w32 + mt * 16 + g;
                af[mt][0] = Qs[r][kk + t];
                af[mt][1] = Qs[r + 8][kk + t];
                af[mt][2] = Qs[r][kk + t + 4];
                af[mt][3] = Qs[r + 8][kk + t + 4];
            }
#pragma unroll
            for (int nt = 0; nt < 8; nt++) {
                unsigned b0 = __float_as_uint(Kr[bu][nt * 8 + g][kk + t]);
                unsigned b1 = __float_as_uint(Kr[bu][nt * 8 + g][kk + t + 4]);
#pragma unroll
                for (int mt = 0; mt < 2; mt++)
                    mma_tf32(sc[mt][nt], af[mt], b0, b1);
            }
        }

        // Online softmax; P (tf32) -> Ss
#pragma unroll
        for (int mt = 0; mt < 2; mt++) {
#pragma unroll
            for (int hi = 0; hi < 2; hi++) {
                const int ri = mt * 2 + hi;
                float pm = -CUDART_INF_F;
#pragma unroll
                for (int nt = 0; nt < 8; nt++) {
                    sc[mt][nt][hi * 2 + 0] *= 0.125f;
                    sc[mt][nt][hi * 2 + 1] *= 0.125f;
                    pm = fmaxf(pm, fmaxf(sc[mt][nt][hi * 2], sc[mt][nt][hi * 2 + 1]));
                }
                pm = fmaxf(pm, __shfl_xor_sync(0xffffffffu, pm, 1));
                pm = fmaxf(pm, __shfl_xor_sync(0xffffffffu, pm, 2));

                float mn = fmaxf(m_i[ri], pm);
                float corr = __expf(m_i[ri] - mn);
                m_i[ri] = mn;

                float ps = 0.f;
                int row = w32 + mt * 16 + g + hi * 8;
#pragma unroll
                for (int nt = 0; nt < 8; nt++) {
                    float p0 = __expf(sc[mt][nt][hi * 2 + 0] - mn);
                    float p1 = __expf(sc[mt][nt][hi * 2 + 1] - mn);
                    ps += p0 + p1;
                    Ss[row][nt * 8 + 2 * t + 0] = f2tf32(p0);
                    Ss[row][nt * 8 + 2 * t + 1] = f2tf32(p1);
                }
                ps += __shfl_xor_sync(0xffffffffu, ps, 1);
                ps += __shfl_xor_sync(0xffffffffu, ps, 2);
                l_i[ri] = l_i[ri] * corr + ps;

#pragma unroll
                for (int nt = 0; nt < 8; nt++) {
                    o[mt][nt][hi * 2 + 0] *= corr;
                    o[mt][nt][hi * 2 + 1] *= corr;
                }
            }
        }
        __syncwarp();

        // O += P V  (V raw tf32 bits)
#pragma unroll
        for (int ks = 0; ks < 8; ks++) {
            const int kk = ks * 8;
            unsigned af[2][4];
#pragma unroll
            for (int mt = 0; mt < 2; mt++) {
                int r = w32 + mt * 16 + g;
                af[mt][0] = Ss[r][kk + t];
                af[mt][1] = Ss[r + 8][kk + t];
                af[mt][2] = Ss[r][kk + t + 4];
                af[mt][3] = Ss[r + 8][kk + t + 4];
            }
#pragma unroll
            for (int nt = 0; nt < 8; nt++) {
                unsigned b0 = __float_as_uint(Vr[bu][kk + t][nt * 8 + g]);
                unsigned b1 = __float_as_uint(Vr[bu][kk + t + 4][nt * 8 + g]);
#pragma unroll
                for (int mt = 0; mt < 2; mt++)
                    mma_tf32(o[mt][nt], af[mt], b0, b1);
            }
        }
    }

    // Epilogue: ctx [B,S,HID] stored as tf32 bits (O-projection consumes)
#pragma unroll
    for (int mt = 0; mt < 2; mt++) {
#pragma unroll
        for (int hi = 0; hi < 2; hi++) {
            const int ri = mt * 2 + hi;
            float inv = 1.f / l_i[ri];
            int srow = qt * 128 + w32 + mt * 16 + g + hi * 8;
#pragma unroll
            for (int nt = 0; nt < 8; nt++) {
                float2 val;
                val.x = __uint_as_float(f2tf32(o[mt][nt][hi * 2 + 0] * inv));
                val.y = __uint_as_float(f2tf32(o[mt][nt][hi * 2 + 1] * inv));
                *(float2*)&ctx[((size_t)b * SEQ + srow) * HID + h * HD + nt * 8 + 2 * t] = val;
            }
        }
    }
}

// ---------------------------------------------------------------------------
extern "C" void kernel_launch(void* const* d_in, const int* in_sizes, int n_in,
                              void* d_out, int out_size)
{
    const float* hidden = (const float*)d_in[0];
    const float* Wq = (const float*)d_in[1];
    const float* bq = (const float*)d_in[2];
    const float* Wk = (const float*)d_in[3];
    const float* bk = (const float*)d_in[4];
    const float* Wv = (const float*)d_in[5];
    const float* bv = (const float*)d_in[6];
    const float* Wo = (const float*)d_in[7];
    const float* bo = (const float*)d_in[8];
    float* out = (float*)d_out;

    float *pQ, *pK, *pV, *pCtx, *pHidT, *pWT;
    cudaGetSymbolAddress((void**)&pQ, g_Q);
    cudaGetSymbolAddress((void**)&pK, g_K);
    cudaGetSymbolAddress((void**)&pV, g_V);
    cudaGetSymbolAddress((void**)&pCtx, g_ctx);
    cudaGetSymbolAddress((void**)&pHidT, g_hidT);
    cudaGetSymbolAddress((void**)&pWT, g_WT);

    // Pre-pass: convert hidden + weights to tf32 bits.
    // (MTOT*HID + 4*HID*HID) / 4 = 2M float4 -> 8192 blocks x 256
    {
        const int total4 = (MTOT * HID + 4 * HID * HID) / 4;
        cvt_tf32_kernel<<<total4 / 256, 256>>>(hidden, Wq, Wk, Wv, Wo,
                                               pHidT, pWT);
    }

    const int gsmem = (2 * 128 * 36 + 2 * 32 * 136) * 4;   // 71,680 B
    cudaFuncSetAttribute(gemm_qkv_kernel,
                         cudaFuncAttributeMaxDynamicSharedMemorySize, gsmem);
    cudaFuncSetAttribute(gemm_out_kernel,
                         cudaFuncAttributeMaxDynamicSharedMemorySize, gsmem);

    // Fused QKV projection (cvt-free mainloop), scatter [B,H,S,D]
    dim3 qgrid(HID / 128, MTOT / 128, 3);   // (8, 32, 3)
    gemm_qkv_kernel<<<qgrid, 256, gsmem>>>(pHidT, pWT, bq, bk, bv,
                                           pQ, pK, pV);

    // Attention
    {
        const int smem_bytes = (128 * 68 + 4 * 64 * 72 + 128 * 68) * 4;  // 143,360
        cudaFuncSetAttribute(attn_tf32_kernel,
                             cudaFuncAttributeMaxDynamicSharedMemorySize,
                             smem_bytes);
        dim3 agrid(SEQ / 128, NH, BSZ);  // (16, 16, 2)
        attn_tf32_kernel<<<agrid, 128, smem_bytes>>>(pQ, pK, pV, pCtx);
    }

    // Output projection (cvt-free mainloop)
    dim3 ogrid(HID / 128, MTOT / 128);
    gemm_out_kernel<<<ogrid, 256, gsmem>>>(pCtx, pWT + 3 * HID * HID, bo, out);
}